// round 16
// baseline (speedup 1.0000x reference)
#include <cuda_runtime.h>

// EHD layer v14 (= v13 + tall tile via 2 stage-B passes + 4x2 sliding D):
//   3x3 conv (8 filters) -> argmax+thresh -> byte-packed one-hot ->
//   separable 5x5 box sum -> magic-number unpack -> out[B,9,1018,1018].
//
// v14 vs v13 (183us best):
//  - index tile 32x64 via TWO sequential stage A/B/C passes (rows r, r+32):
//    same 4px/thread/48-reg inner loop, halo 1.31x->1.22x, grid 21904->10064.
//  - stage D: 4-row x 2-col sliding blocks (210 units, one pass):
//    8 LDS.128 + 20 u64 adds per 8 px (was 12 + 24).
//  - still exactly one __syncthreads.

#define NOR    8
#define NBINS  9
#define OUT_H  1018
#define OUT_W  1018
#define THRESH 0.9f

#define TW  28            // output tile width
#define TH  60            // output tile height
#define ITH 64            // index tile height (2 passes x 32)

#define NTHREADS 256

typedef unsigned long long u64;

__constant__ float c_masks[NOR * 9];

__device__ __forceinline__ float cnt_scale(unsigned word, int byte_sel) {
    // word's byte[byte_sel] = count in 0..25 -> count * fl(1/25), exact
    const unsigned bits = __byte_perm(word, 0x4B000000u, 0x7440 | byte_sel);
    return fmaf(__int_as_float(bits), (1.0f / 25.0f),
                -(8388608.0f * (1.0f / 25.0f)));
}

__global__ __launch_bounds__(NTHREADS, 5)
void ehd_fused_kernel(const float* __restrict__ x,
                      float* __restrict__ out)
{
    __shared__ u64 s_h[ITH][36];   // horizontal 5-sums (16B-aligned even cols)

    const int tid  = threadIdx.x;
    const int lane = tid & 31;
    const int ox   = blockIdx.x * TW;
    const int oy   = blockIdx.y * TH;
    const int b    = blockIdx.z;

    const int c0 = (tid & 7) << 2;    // index col group (0,4,...,28)
    const int gx = ox + c0;           // global col of first px (mult of 4)

    const float* xb = x + (size_t)b * (1024 * 1024);
    const bool has_nbr = ((lane & 7) != 7);
    const bool fastw   = (ox + 34 <= 1024);

    // ==== stages A/B/C, two passes over 32 index rows each ====
#pragma unroll
    for (int pass = 0; pass < 2; pass++) {
        const int r  = (tid >> 3) + (pass << 5);   // index row 0..63
        const int gy = oy + r;

        // ---- stage A: load 3x6 input window straight from global ----
        float w[3][6];
        if (fastw && gy + 3 <= 1024) {
            // fast path (warp-uniform: gy+3 uniform per warp-row grouping;
            // rows of 8 threads share gy, branch is row-uniform)
#pragma unroll
            for (int j = 0; j < 3; j++) {
                const float* row = xb + (gy + j) * 1024 + gx;
                const float4 a = *(const float4*)row;       // gx multiple of 4
                const float2 bb = *(const float2*)(row + 4);
                w[j][0] = a.x; w[j][1] = a.y; w[j][2] = a.z;
                w[j][3] = a.w; w[j][4] = bb.x; w[j][5] = bb.y;
            }
        } else {
            // slow path: per-element predicated, zero-fill OOB. OOB zeros
            // only feed index px whose outputs are clipped below.
#pragma unroll
            for (int j = 0; j < 3; j++) {
                const int yy = gy + j;
                const bool yv = (yy < 1024);
                const float* row = xb + yy * 1024 + gx;
#pragma unroll
                for (int k = 0; k < 6; k++)
                    w[j][k] = (yv && (gx + k < 1024)) ? row[k] : 0.0f;
            }
        }

        // ---- stage B: conv (8 filters) + argmax + threshold, 4 px ----
        float best[4];
        int   bi[4];
#pragma unroll
        for (int q = 0; q < 4; q++) { best[q] = -3.4e38f; bi[q] = 0; }

#pragma unroll
        for (int f = 0; f < NOR; f++) {
            const float m0 = c_masks[f * 9 + 0], m1 = c_masks[f * 9 + 1], m2 = c_masks[f * 9 + 2];
            const float m3 = c_masks[f * 9 + 3], m4 = c_masks[f * 9 + 4], m5 = c_masks[f * 9 + 5];
            const float m6 = c_masks[f * 9 + 6], m7 = c_masks[f * 9 + 7], m8 = c_masks[f * 9 + 8];
#pragma unroll
            for (int q = 0; q < 4; q++) {
                float acc = w[0][q] * m0;
                acc = fmaf(w[0][q + 1], m1, acc);
                acc = fmaf(w[0][q + 2], m2, acc);
                acc = fmaf(w[1][q    ], m3, acc);
                acc = fmaf(w[1][q + 1], m4, acc);
                acc = fmaf(w[1][q + 2], m5, acc);
                acc = fmaf(w[2][q    ], m6, acc);
                acc = fmaf(w[2][q + 1], m7, acc);
                acc = fmaf(w[2][q + 2], m8, acc);
                // strict > keeps FIRST max (jnp.argmax tie-break)
                if (acc > best[q]) { best[q] = acc; bi[q] = f; }
            }
        }

        // byte-packed one-hot: bins 0..7 -> one byte of a u64; bin 8 implicit
        u64 oh[4];
#pragma unroll
        for (int q = 0; q < 4; q++) {
            const int idx = (best[q] < THRESH) ? NOR : bi[q];
            oh[q] = (idx < NOR) ? (1ULL << (idx << 3)) : 0ULL;
        }

        // ---- stage C: horizontal 5-tap via shfl (neighbor quad = lane+1) ----
        u64 n[4];
#pragma unroll
        for (int q = 0; q < 4; q++) {
            const u64 t = __shfl_down_sync(0xFFFFFFFFu, oh[q], 1);
            n[q] = has_nbr ? t : 0ULL;
        }
        const u64 h0 = oh[0] + oh[1] + oh[2] + oh[3] + n[0];
        const u64 h1 = h0 - oh[0] + n[1];
        const u64 h2 = h1 - oh[1] + n[2];
        const u64 h3 = h2 - oh[2] + n[3];
        ulonglong2* dst = (ulonglong2*)&s_h[r][c0];
        dst[0] = make_ulonglong2(h0, h1);
        dst[1] = make_ulonglong2(h2, h3);
    }
    __syncthreads();   // the only barrier

    // ==== stage D: 4-row x 2-col sliding blocks ====
    // units: 15 row-quads x 14 col-pairs = 210 (single pass).
    // v(r+1) = v(r) - h(r) + h(r+5); 8 LDS.128 per 8 px.
    if (tid < 15 * 14) {
        const int rq = tid / 14;
        const int cp = tid - rq * 14;
        const int rr = rq << 2;          // 0..56
        const int cc = cp << 1;
        const int oyy = oy + rr, oxx = ox + cc;
        if (oxx + 1 < OUT_W) {
            const ulonglong2 q0 = *(const ulonglong2*)&s_h[rr    ][cc];
            const ulonglong2 q1 = *(const ulonglong2*)&s_h[rr + 1][cc];
            const ulonglong2 q2 = *(const ulonglong2*)&s_h[rr + 2][cc];
            const ulonglong2 q3 = *(const ulonglong2*)&s_h[rr + 3][cc];
            const ulonglong2 q4 = *(const ulonglong2*)&s_h[rr + 4][cc];
            const ulonglong2 q5 = *(const ulonglong2*)&s_h[rr + 5][cc];
            const ulonglong2 q6 = *(const ulonglong2*)&s_h[rr + 6][cc];
            const ulonglong2 q7 = *(const ulonglong2*)&s_h[rr + 7][cc];

            u64 v0[4], v1[4];   // [row] per column of the pair
            v0[0] = q0.x + q1.x + q2.x + q3.x + q4.x;
            v1[0] = q0.y + q1.y + q2.y + q3.y + q4.y;
            v0[1] = v0[0] - q0.x + q5.x;
            v1[1] = v1[0] - q0.y + q5.y;
            v0[2] = v0[1] - q1.x + q6.x;
            v1[2] = v1[1] - q1.y + q6.y;
            v0[3] = v0[2] - q2.x + q7.x;
            v1[3] = v1[2] - q2.y + q7.y;

            const size_t plane = (size_t)OUT_H * OUT_W;
            float* pa = out + (size_t)b * NBINS * plane
                            + (size_t)oyy * OUT_W + oxx;
#pragma unroll
            for (int k = 0; k < 4; k++) {
                if (oyy + k < OUT_H) {
                    const unsigned lo0 = (unsigned)v0[k], hi0 = (unsigned)(v0[k] >> 32);
                    const unsigned lo1 = (unsigned)v1[k], hi1 = (unsigned)(v1[k] >> 32);
                    float* p = pa + (size_t)k * OUT_W;
#pragma unroll
                    for (int bin = 0; bin < 8; bin++) {
                        const int sel = bin & 3;
                        float2 v;
                        v.x = cnt_scale((bin < 4) ? lo0 : hi0, sel);
                        v.y = cnt_scale((bin < 4) ? lo1 : hi1, sel);
                        *(float2*)(p + (size_t)bin * plane) = v;
                    }
                    // bin 8 = 25 - sum of the other 8 counts
                    float2 v8;
                    v8.x = cnt_scale(25u - __dp4a(lo0, 0x01010101u, __dp4a(hi0, 0x01010101u, 0u)), 0);
                    v8.y = cnt_scale(25u - __dp4a(lo1, 0x01010101u, __dp4a(hi1, 0x01010101u, 0u)), 0);
                    *(float2*)(p + (size_t)8 * plane) = v8;
                }
            }
        }
    }
}

extern "C" void kernel_launch(void* const* d_in, const int* in_sizes, int n_in,
                              void* d_out, int out_size)
{
    const float* x     = (const float*)d_in[0];   // [B,1,1024,1024]
    const float* masks = (const float*)d_in[1];   // [8,1,3,3]
    float* out = (float*)d_out;                   // [B,9,1018,1018]

    const int batch = in_sizes[0] / (1024 * 1024);

    // masks -> constant bank (device-to-device async copy: graph-capturable)
    cudaMemcpyToSymbolAsync(c_masks, masks, NOR * 9 * sizeof(float), 0,
                            cudaMemcpyDeviceToDevice);

    dim3 grid((OUT_W + TW - 1) / TW, (OUT_H + TH - 1) / TH, batch);
    ehd_fused_kernel<<<grid, NTHREADS>>>(x, out);
}

// round 17
// speedup vs baseline: 1.2039x; 1.2039x over previous
#include <cuda_runtime.h>

// EHD layer v15 (= v13 best + smem masks instead of constant bank):
//   3x3 conv (8 filters) -> argmax+thresh -> byte-packed one-hot ->
//   separable 5x5 box sum -> magic-number unpack -> out[B,9,1018,1018].
//
// v15 vs v13 (183us):
//  - masks in SMEM, read as 2xLDS.128 + LDS.32 per filter (3 issues,
//    broadcast, LDS floor 2) instead of 9 scalar LDC (floor 8/SMSP on
//    sm_103a's half-rate constant port; 72 LDC/thread/tile was a hidden
//    serialized cost).
//  - adds one early barrier (mask store -> stage B); stage A LDGs overlap it.

#define NOR    8
#define NBINS  9
#define OUT_H  1018
#define OUT_W  1018
#define THRESH 0.9f

#define T   28            // output tile
#define IT  32            // index tile (T+4)

#define NTHREADS 256

typedef unsigned long long u64;

__device__ __forceinline__ float cnt_scale(unsigned word, int byte_sel) {
    // word's byte[byte_sel] = count in 0..25 -> count * fl(1/25), exact
    const unsigned bits = __byte_perm(word, 0x4B000000u, 0x7440 | byte_sel);
    return fmaf(__int_as_float(bits), (1.0f / 25.0f),
                -(8388608.0f * (1.0f / 25.0f)));
}

__global__ __launch_bounds__(NTHREADS, 5)
void ehd_fused_kernel(const float* __restrict__ x,
                      const float* __restrict__ masks,
                      float* __restrict__ out)
{
    __shared__ u64 s_h[IT][36];             // horizontal 5-sums
    __shared__ __align__(16) float s_m[NOR * 12];  // filter f at f*12, taps 0..8

    const int tid  = threadIdx.x;
    const int lane = tid & 31;
    const int ox   = blockIdx.x * T;
    const int oy   = blockIdx.y * T;
    const int b    = blockIdx.z;

    if (tid < NOR * 9) {
        const int f = tid / 9, j = tid - f * 9;
        s_m[f * 12 + j] = masks[tid];
    }

    const int r  = tid >> 3;          // index row within tile (0..31)
    const int c0 = (tid & 7) << 2;    // index col group (0,4,...,28)
    const int gx = ox + c0;           // global col of first px (mult of 4)
    const int gy = oy + r;            // global row of index px

    const float* xb = x + (size_t)b * (1024 * 1024);

    // ---- stage A: load 3x6 input window straight from global ----
    float w[3][6];
    if (ox + 34 <= 1024 && oy + 34 <= 1024) {
        // fast path: whole 34x34 input footprint in-bounds (36/37 tiles each way)
#pragma unroll
        for (int j = 0; j < 3; j++) {
            const float* row = xb + (gy + j) * 1024 + gx;
            const float4 a = *(const float4*)row;       // gx multiple of 4
            const float2 bb = *(const float2*)(row + 4);
            w[j][0] = a.x; w[j][1] = a.y; w[j][2] = a.z;
            w[j][3] = a.w; w[j][4] = bb.x; w[j][5] = bb.y;
        }
    } else {
        // slow path (edge tiles): per-element predicated, zero-fill OOB.
        // OOB zeros only feed index px whose outputs are clipped below.
#pragma unroll
        for (int j = 0; j < 3; j++) {
            const int yy = gy + j;
            const bool yv = (yy < 1024);
            const float* row = xb + yy * 1024 + gx;
#pragma unroll
            for (int k = 0; k < 6; k++)
                w[j][k] = (yv && (gx + k < 1024)) ? row[k] : 0.0f;
        }
    }

    __syncthreads();   // masks visible (stage A LDGs already in flight)

    // ---- stage B: conv (8 filters) + argmax + threshold, 4 horizontal px ----
    float best[4];
    int   bi[4];
#pragma unroll
    for (int q = 0; q < 4; q++) { best[q] = -3.4e38f; bi[q] = 0; }

#pragma unroll
    for (int f = 0; f < NOR; f++) {
        const float4 qa = *(const float4*)&s_m[f * 12];      // m0..m3
        const float4 qb = *(const float4*)&s_m[f * 12 + 4];  // m4..m7
        const float  m8 = s_m[f * 12 + 8];
#pragma unroll
        for (int q = 0; q < 4; q++) {
            float acc = w[0][q] * qa.x;
            acc = fmaf(w[0][q + 1], qa.y, acc);
            acc = fmaf(w[0][q + 2], qa.z, acc);
            acc = fmaf(w[1][q    ], qa.w, acc);
            acc = fmaf(w[1][q + 1], qb.x, acc);
            acc = fmaf(w[1][q + 2], qb.y, acc);
            acc = fmaf(w[2][q    ], qb.z, acc);
            acc = fmaf(w[2][q + 1], qb.w, acc);
            acc = fmaf(w[2][q + 2], m8,   acc);
            // strict > keeps FIRST max (jnp.argmax tie-break)
            if (acc > best[q]) { best[q] = acc; bi[q] = f; }
        }
    }

    // byte-packed one-hot: bins 0..7 -> one byte of a u64; bin 8 implicit
    u64 oh[4];
#pragma unroll
    for (int q = 0; q < 4; q++) {
        const int idx = (best[q] < THRESH) ? NOR : bi[q];
        oh[q] = (idx < NOR) ? (1ULL << (idx << 3)) : 0ULL;
    }

    // ---- stage C: horizontal 5-tap via shfl (neighbor quad = lane+1) ----
    const bool has_nbr = ((lane & 7) != 7);
    u64 n[4];
#pragma unroll
    for (int q = 0; q < 4; q++) {
        const u64 t = __shfl_down_sync(0xFFFFFFFFu, oh[q], 1);
        n[q] = has_nbr ? t : 0ULL;
    }
    const u64 h0 = oh[0] + oh[1] + oh[2] + oh[3] + n[0];
    const u64 h1 = h0 - oh[0] + n[1];
    const u64 h2 = h1 - oh[1] + n[2];
    const u64 h3 = h2 - oh[2] + n[3];
    {
        ulonglong2* dst = (ulonglong2*)&s_h[r][c0];
        dst[0] = make_ulonglong2(h0, h1);
        dst[1] = make_ulonglong2(h2, h3);
    }
    __syncthreads();

    // ---- stage D: 2x2 output block per thread, sliding vertical 5-tap ----
    // rp = tid>>4 (row pair), cp = tid&15 (col pair); active: rp<14, cp<14.
    // v(r+1) = v(r) - h(r) + h(r+5): 6 LDS.128 + 12 u64 adds per 4 px.
    {
        const int rp = tid >> 4;
        const int cp = tid & 15;
        const int rr = rp << 1;
        const int cc = cp << 1;
        const int oyy = oy + rr, oxx = ox + cc;
        if (rp < 14 && cp < 14 && oyy < OUT_H && oxx + 1 < OUT_W) {
            const ulonglong2 q0 = *(const ulonglong2*)&s_h[rr    ][cc];
            const ulonglong2 q1 = *(const ulonglong2*)&s_h[rr + 1][cc];
            const ulonglong2 q2 = *(const ulonglong2*)&s_h[rr + 2][cc];
            const ulonglong2 q3 = *(const ulonglong2*)&s_h[rr + 3][cc];
            const ulonglong2 q4 = *(const ulonglong2*)&s_h[rr + 4][cc];
            const ulonglong2 q5 = *(const ulonglong2*)&s_h[rr + 5][cc];

            const u64 va0 = q0.x + q1.x + q2.x + q3.x + q4.x;
            const u64 va1 = q0.y + q1.y + q2.y + q3.y + q4.y;
            const u64 vb0 = va0 - q0.x + q5.x;
            const u64 vb1 = va1 - q0.y + q5.y;

            const unsigned alo0 = (unsigned)va0, ahi0 = (unsigned)(va0 >> 32);
            const unsigned alo1 = (unsigned)va1, ahi1 = (unsigned)(va1 >> 32);
            const unsigned blo0 = (unsigned)vb0, bhi0 = (unsigned)(vb0 >> 32);
            const unsigned blo1 = (unsigned)vb1, bhi1 = (unsigned)(vb1 >> 32);

            const size_t plane = (size_t)OUT_H * OUT_W;
            float* pa = out + (size_t)b * NBINS * plane + (size_t)oyy * OUT_W + oxx;
            const bool row2 = (oyy + 1 < OUT_H);

#pragma unroll
            for (int bin = 0; bin < 8; bin++) {
                const int sel = bin & 3;
                float2 va, vb;
                va.x = cnt_scale((bin < 4) ? alo0 : ahi0, sel);
                va.y = cnt_scale((bin < 4) ? alo1 : ahi1, sel);
                float* qp = pa + (size_t)bin * plane;
                *(float2*)qp = va;
                if (row2) {
                    vb.x = cnt_scale((bin < 4) ? blo0 : bhi0, sel);
                    vb.y = cnt_scale((bin < 4) ? blo1 : bhi1, sel);
                    *(float2*)(qp + OUT_W) = vb;
                }
            }
            // bin 8 = 25 - sum of the other 8 counts
            float2 v8a;
            v8a.x = cnt_scale(25u - __dp4a(alo0, 0x01010101u, __dp4a(ahi0, 0x01010101u, 0u)), 0);
            v8a.y = cnt_scale(25u - __dp4a(alo1, 0x01010101u, __dp4a(ahi1, 0x01010101u, 0u)), 0);
            float* q8 = pa + (size_t)8 * plane;
            *(float2*)q8 = v8a;
            if (row2) {
                float2 v8b;
                v8b.x = cnt_scale(25u - __dp4a(blo0, 0x01010101u, __dp4a(bhi0, 0x01010101u, 0u)), 0);
                v8b.y = cnt_scale(25u - __dp4a(blo1, 0x01010101u, __dp4a(bhi1, 0x01010101u, 0u)), 0);
                *(float2*)(q8 + OUT_W) = v8b;
            }
        }
    }
}

extern "C" void kernel_launch(void* const* d_in, const int* in_sizes, int n_in,
                              void* d_out, int out_size)
{
    const float* x     = (const float*)d_in[0];   // [B,1,1024,1024]
    const float* masks = (const float*)d_in[1];   // [8,1,3,3]
    float* out = (float*)d_out;                   // [B,9,1018,1018]

    const int batch = in_sizes[0] / (1024 * 1024);

    dim3 grid((OUT_W + T - 1) / T, (OUT_H + T - 1) / T, batch);
    ehd_fused_kernel<<<grid, NTHREADS>>>(x, masks, out);
}